// round 6
// baseline (speedup 1.0000x reference)
#include <cuda_runtime.h>
#include <cuda_bf16.h>

// URPE: out[b,h,i,j] = attention_probs[b,h,i,j] * toe[h,i,j]
// toe[h,i,j] = w[h, L + j - i] if j >= i else w[h, i - j].
//
// B=2, H=16, L=2048. HBM-bound streaming multiply (512 MB in + 512 MB out),
// traffic at its 1.074 GB floor; measured ceiling so far ~6.69 TB/s.
// R5: persistent grid (1 wave, 1184 CTAs) + software-pipelined double buffer:
// loads of chunk n+1 are in flight while chunk n is multiplied and stored.
// Removes ~27 wave transitions and keeps LDG issue continuous.

static constexpr int LDIM = 2048;
static constexpr int HDIM = 16;
static constexpr int BDIM = 2;
static constexpr int VEC_PER_ROW = LDIM / 4;            // 512 float4 per row
static constexpr long long NVEC =
    (long long)BDIM * HDIM * LDIM * LDIM / 4;           // 33,554,432
static constexpr int THREADS = 256;
static constexpr int ILP = 4;                           // float4s per chunk-slot
static constexpr int CHUNK = THREADS * ILP;             // 1024 vec per chunk
static constexpr unsigned int NCHUNK =
    (unsigned int)(NVEC / CHUNK);                       // 32768
static constexpr int GRID = 148 * 8;                    // 1184 = ~one full wave

__device__ __forceinline__ void weight_mul(float4& v, unsigned int vid,
                                           const float* __restrict__ w) {
    int j0 = (vid & (VEC_PER_ROW - 1)) << 2;
    int i  = (vid >> 9)  & (LDIM - 1);
    int h  = (vid >> 20) & (HDIM - 1);
    const float* __restrict__ wh = w + h * (2 * LDIM);

    int d = j0 - i;
    int d0 = d,     o0 = (d0 >= 0) ? (LDIM + d0) : -d0;
    int d1 = d + 1, o1 = (d1 >= 0) ? (LDIM + d1) : -d1;
    int d2 = d + 2, o2 = (d2 >= 0) ? (LDIM + d2) : -d2;
    int d3 = d + 3, o3 = (d3 >= 0) ? (LDIM + d3) : -d3;

    v.x *= __ldg(wh + o0);
    v.y *= __ldg(wh + o1);
    v.z *= __ldg(wh + o2);
    v.w *= __ldg(wh + o3);
}

__global__ __launch_bounds__(THREADS)
void urpe_mul_kernel(const float4* __restrict__ probs,
                     const float*  __restrict__ w,
                     float4*       __restrict__ out) {
    const int tid = threadIdx.x;
    unsigned int chunk = blockIdx.x;

    if (chunk >= NCHUNK) return;

    // Prologue: load chunk 0 of this CTA's strided sequence.
    float4 v[ILP];
    {
        unsigned int base = chunk * CHUNK + tid;
#pragma unroll
        for (int k = 0; k < ILP; k++)
            v[k] = __ldcs(&probs[base + k * THREADS]);
    }

    // Pipelined mainloop: issue next chunk's loads, then finish current chunk.
    for (unsigned int next = chunk + GRID; next < NCHUNK; next += GRID) {
        float4 u[ILP];
        unsigned int nbase = next * CHUNK + tid;
#pragma unroll
        for (int k = 0; k < ILP; k++)
            u[k] = __ldcs(&probs[nbase + k * THREADS]);

        unsigned int base = chunk * CHUNK + tid;
#pragma unroll
        for (int k = 0; k < ILP; k++) {
            unsigned int vid = base + k * THREADS;
            weight_mul(v[k], vid, w);
            __stcs(&out[vid], v[k]);
        }

#pragma unroll
        for (int k = 0; k < ILP; k++) v[k] = u[k];
        chunk = next;
    }

    // Epilogue: finish last chunk.
    {
        unsigned int base = chunk * CHUNK + tid;
#pragma unroll
        for (int k = 0; k < ILP; k++) {
            unsigned int vid = base + k * THREADS;
            weight_mul(v[k], vid, w);
            __stcs(&out[vid], v[k]);
        }
    }
}

extern "C" void kernel_launch(void* const* d_in, const int* in_sizes, int n_in,
                              void* d_out, int out_size) {
    const float4* probs = (const float4*)d_in[0];   // attention_probs [B,H,L,L] f32
    const float*  w     = (const float*)d_in[1];    // urpe_weight_    [H,2L]   f32
    float4*       out   = (float4*)d_out;

    urpe_mul_kernel<<<GRID, THREADS>>>(probs, w, out);
}

// round 7
// speedup vs baseline: 1.1699x; 1.1699x over previous
#include <cuda_runtime.h>
#include <cuda_bf16.h>

// URPE: out[b,h,i,j] = attention_probs[b,h,i,j] * toe[h,i,j]
// toe[h,i,j] = w[h, L + j - i] if j >= i else w[h, i - j].
//
// B=2, H=16, L=2048. HBM-bound streaming multiply, traffic at its 1.074 GB
// floor. Measured ceiling across 5 kernel shapes: ~6.69 TB/s (84% of spec).
// R6 = best-known configuration (R1: ILP=4 front-batched float4 stream,
// streaming cache hints, L2-hot weight gathers), micro-cleaned:
// exact grid (no bounds branch), unsigned index math, fused mul+store.

static constexpr int LDIM = 2048;
static constexpr int HDIM = 16;
static constexpr int BDIM = 2;
static constexpr int VEC_PER_ROW = LDIM / 4;            // 512 float4 per row
static constexpr long long NVEC =
    (long long)BDIM * HDIM * LDIM * LDIM / 4;           // 33,554,432
static constexpr int THREADS = 256;
static constexpr int ILP = 4;                           // float4s per thread

__global__ __launch_bounds__(THREADS)
void urpe_mul_kernel(const float4* __restrict__ probs,
                     const float*  __restrict__ w,
                     float4*       __restrict__ out) {
    // Block covers ILP*THREADS = 1024 consecutive float4 (2 full rows).
    // Thread t owns vids base + k*256 — each instruction wave is a fully
    // coalesced 4 KB burst.
    const unsigned int base = blockIdx.x * (THREADS * ILP) + threadIdx.x;

    // Phase 1: front-batch all 4 independent stream loads (LDG.128.CS,
    // MLP_p1 = 4 — measured to saturate the DRAM request pipe).
    float4 v[ILP];
#pragma unroll
    for (int k = 0; k < ILP; k++)
        v[k] = __ldcs(&probs[base + k * THREADS]);

    // Phase 2: weight gather (256 KB table, L1/L2-hot), multiply, store.
#pragma unroll
    for (int k = 0; k < ILP; k++) {
        const unsigned int vid = base + k * THREADS;
        const unsigned int j0 = (vid & (VEC_PER_ROW - 1)) << 2;
        const unsigned int i  = (vid >> 9)  & (LDIM - 1);
        const unsigned int h  = (vid >> 20) & (HDIM - 1);
        const float* __restrict__ wh = w + h * (2 * LDIM);

        const int d = (int)j0 - (int)i;
        const int d0 = d,     o0 = (d0 >= 0) ? (LDIM + d0) : -d0;
        const int d1 = d + 1, o1 = (d1 >= 0) ? (LDIM + d1) : -d1;
        const int d2 = d + 2, o2 = (d2 >= 0) ? (LDIM + d2) : -d2;
        const int d3 = d + 3, o3 = (d3 >= 0) ? (LDIM + d3) : -d3;

        v[k].x *= __ldg(wh + o0);
        v[k].y *= __ldg(wh + o1);
        v[k].z *= __ldg(wh + o2);
        v[k].w *= __ldg(wh + o3);

        __stcs(&out[vid], v[k]);
    }
}

extern "C" void kernel_launch(void* const* d_in, const int* in_sizes, int n_in,
                              void* d_out, int out_size) {
    const float4* probs = (const float4*)d_in[0];   // attention_probs [B,H,L,L] f32
    const float*  w     = (const float*)d_in[1];    // urpe_weight_    [H,2L]   f32
    float4*       out   = (float4*)d_out;

    const int blocks = (int)(NVEC / (THREADS * ILP));  // 32768, exact
    urpe_mul_kernel<<<blocks, THREADS>>>(probs, w, out);
}

// round 8
// speedup vs baseline: 1.1795x; 1.0082x over previous
#include <cuda_runtime.h>

// URPE: out[b,h,i,j] = attention_probs[b,h,i,j] * toe[h,i,j]
// toe[h,i,j] = w[h, L + j - i] if j >= i else w[h, i - j].
//
// B=2, H=16, L=2048. HBM-bound streaming multiply; traffic at its 1.074 GB
// algorithmic floor (full f32 tensor in + out, no reuse). Measured across six
// kernel shapes: achieved ceiling ~6.73 TB/s (85% of 8 TB/s spec). This is
// the best-measured configuration (R6): ILP=4 front-batched LDG.128.CS
// stream, L1/L2-hot scalar weight gathers, fused multiply + STG.128.CS.

static constexpr int LDIM = 2048;
static constexpr int HDIM = 16;
static constexpr int BDIM = 2;
static constexpr int VEC_PER_ROW = LDIM / 4;            // 512 float4 per row
static constexpr long long NVEC =
    (long long)BDIM * HDIM * LDIM * LDIM / 4;           // 33,554,432
static constexpr int THREADS = 256;
static constexpr int ILP = 4;                           // float4s per thread

__global__ __launch_bounds__(THREADS)
void urpe_mul_kernel(const float4* __restrict__ probs,
                     const float*  __restrict__ w,
                     float4*       __restrict__ out) {
    // Block covers ILP*THREADS = 1024 consecutive float4 (2 full rows).
    // Thread t owns vids base + k*256 — each instruction wave is a fully
    // coalesced 4 KB burst.
    const unsigned int base = blockIdx.x * (THREADS * ILP) + threadIdx.x;

    // Phase 1: front-batch all 4 independent stream loads (LDG.128.CS,
    // MLP_p1 = 4 — measured to saturate the DRAM request pipe).
    float4 v[ILP];
#pragma unroll
    for (int k = 0; k < ILP; k++)
        v[k] = __ldcs(&probs[base + k * THREADS]);

    // Phase 2: weight gather (256 KB table, L1/L2-hot), multiply, store.
#pragma unroll
    for (int k = 0; k < ILP; k++) {
        const unsigned int vid = base + k * THREADS;
        const unsigned int j0 = (vid & (VEC_PER_ROW - 1)) << 2;
        const unsigned int i  = (vid >> 9)  & (LDIM - 1);
        const unsigned int h  = (vid >> 20) & (HDIM - 1);
        const float* __restrict__ wh = w + h * (2 * LDIM);

        const int d = (int)j0 - (int)i;
        const int d0 = d,     o0 = (d0 >= 0) ? (LDIM + d0) : -d0;
        const int d1 = d + 1, o1 = (d1 >= 0) ? (LDIM + d1) : -d1;
        const int d2 = d + 2, o2 = (d2 >= 0) ? (LDIM + d2) : -d2;
        const int d3 = d + 3, o3 = (d3 >= 0) ? (LDIM + d3) : -d3;

        v[k].x *= __ldg(wh + o0);
        v[k].y *= __ldg(wh + o1);
        v[k].z *= __ldg(wh + o2);
        v[k].w *= __ldg(wh + o3);

        __stcs(&out[vid], v[k]);
    }
}

extern "C" void kernel_launch(void* const* d_in, const int* in_sizes, int n_in,
                              void* d_out, int out_size) {
    const float4* probs = (const float4*)d_in[0];   // attention_probs [B,H,L,L] f32
    const float*  w     = (const float*)d_in[1];    // urpe_weight_    [H,2L]   f32
    float4*       out   = (float4*)d_out;

    const int blocks = (int)(NVEC / (THREADS * ILP));  // 32768, exact
    urpe_mul_kernel<<<blocks, THREADS>>>(probs, w, out);
}